// round 1
// baseline (speedup 1.0000x reference)
#include <cuda_runtime.h>
#include <cuda_bf16.h>
#include <cstdint>

// Shapes
#define B_SZ   64
#define C_IN   64
#define C_OUT  128
#define H_IN   64
#define W_IN   64
#define H_OUT  62
#define W_OUT  62
#define PIX_PER_IMG (H_OUT * W_OUT)            // 3844
#define NPIX  (B_SZ * PIX_PER_IMG)             // 246016

// Scratch: u0 in pixel-major layout [p][128]  (126 MB, static device array)
__device__ float g_u0[(size_t)NPIX * C_OUT];

// ---------------------------------------------------------------------------
// helpers
// ---------------------------------------------------------------------------
__device__ __forceinline__ unsigned pack_bf16(float hi, float lo) {
    unsigned r;
    asm("cvt.rn.bf16x2.f32 %0, %1, %2;" : "=r"(r) : "f"(hi), "f"(lo));
    return r;
}
__device__ __forceinline__ unsigned sm_u32(const void* p) {
    return (unsigned)__cvta_generic_to_shared(p);
}
__device__ __forceinline__ void ldmatrix_x4(unsigned& r0, unsigned& r1,
                                            unsigned& r2, unsigned& r3,
                                            unsigned addr) {
    asm volatile("ldmatrix.sync.aligned.m8n8.x4.shared.b16 {%0,%1,%2,%3}, [%4];"
                 : "=r"(r0), "=r"(r1), "=r"(r2), "=r"(r3) : "r"(addr));
}
__device__ __forceinline__ void mma_bf16(float& d0, float& d1, float& d2, float& d3,
                                         unsigned a0, unsigned a1, unsigned a2, unsigned a3,
                                         unsigned b0, unsigned b1) {
    asm volatile(
        "mma.sync.aligned.m16n8k16.row.col.f32.bf16.bf16.f32 "
        "{%0,%1,%2,%3}, {%4,%5,%6,%7}, {%8,%9}, {%0,%1,%2,%3};"
        : "+f"(d0), "+f"(d1), "+f"(d2), "+f"(d3)
        : "r"(a0), "r"(a1), "r"(a2), "r"(a3), "r"(b0), "r"(b1));
}

// ---------------------------------------------------------------------------
// Conv kernel: u0_t[p][o] = sum_{c,ky,kx} x[b][c][y+ky][x+kx] * Wff[o][c][ky][kx]
// Grid (62, 64): one output row per block, all 128 oc, fp32 direct conv.
// ---------------------------------------------------------------------------
__global__ __launch_bounds__(256)
void conv_kernel(const float* __restrict__ x, const float* __restrict__ wff) {
    __shared__ float xs[8][3][64];     // 6 KB
    __shared__ float ws[128][72];      // 36 KB
    const int tid = threadIdx.x;
    const int y = blockIdx.x, b = blockIdx.y;
    const int tx = tid & 15;           // column group: cols 4tx..4tx+3
    const int ty = tid >> 4;           // oc octet: oc 8ty..8ty+7

    float acc[8][4];
#pragma unroll
    for (int j = 0; j < 8; j++)
#pragma unroll
        for (int e = 0; e < 4; e++) acc[j][e] = 0.0f;

    const float* xb = x + (size_t)b * C_IN * H_IN * W_IN;

    for (int ic0 = 0; ic0 < C_IN; ic0 += 8) {
        // load input rows y..y+2 for 8 input channels
        for (int t = tid; t < 8 * 3 * 64; t += 256) {
            int i = t / 192, r = (t % 192) / 64, c = t & 63;
            xs[i][r][c] = xb[(size_t)(ic0 + i) * (H_IN * W_IN) + (y + r) * W_IN + c];
        }
        // load weights: 128 oc x 8 ic x 9
        for (int t = tid; t < 128 * 72; t += 256) {
            int o = t / 72, q = t % 72;
            ws[o][q] = wff[o * 576 + ic0 * 9 + q];
        }
        __syncthreads();

#pragma unroll
        for (int i = 0; i < 8; i++) {
#pragma unroll
            for (int r = 0; r < 3; r++) {
                float xv[6];
#pragma unroll
                for (int e = 0; e < 6; e++) {
                    int c = 4 * tx + e;
                    xv[e] = xs[i][r][c > 63 ? 63 : c];  // clamp; masked at write
                }
#pragma unroll
                for (int kx = 0; kx < 3; kx++) {
#pragma unroll
                    for (int j = 0; j < 8; j++) {
                        float wv = ws[8 * ty + j][i * 9 + r * 3 + kx];
                        acc[j][0] = fmaf(xv[kx + 0], wv, acc[j][0]);
                        acc[j][1] = fmaf(xv[kx + 1], wv, acc[j][1]);
                        acc[j][2] = fmaf(xv[kx + 2], wv, acc[j][2]);
                        acc[j][3] = fmaf(xv[kx + 3], wv, acc[j][3]);
                    }
                }
            }
        }
        __syncthreads();
    }

    // write pixel-major u0_t
    const int p_base = b * PIX_PER_IMG + y * W_OUT;
#pragma unroll
    for (int xi = 0; xi < 4; xi++) {
        int xcol = 4 * tx + xi;
        if (xcol < W_OUT) {
            float* dst = g_u0 + (size_t)(p_base + xcol) * C_OUT + 8 * ty;
            float4 v0 = make_float4(acc[0][xi], acc[1][xi], acc[2][xi], acc[3][xi]);
            float4 v1 = make_float4(acc[4][xi], acc[5][xi], acc[6][xi], acc[7][xi]);
            reinterpret_cast<float4*>(dst)[0] = v0;
            reinterpret_cast<float4*>(dst)[1] = v1;
        }
    }
}

// ---------------------------------------------------------------------------
// Fixed-point iteration kernel (persistent per block of 16 pixels).
// Block = 128 threads = 4 warps; warp w owns out-channels [32w, 32w+32).
// u held in mma D-fragments (fp32); a exchanged via double-buffered SMEM (bf16).
// Per-block stopping rule replicates the reference's ||du||/||u|| < 1e-4.
// ---------------------------------------------------------------------------
__global__ __launch_bounds__(128, 2)
void iter_kernel(const float* __restrict__ wrec, const float* __restrict__ thrg,
                 float* __restrict__ out) {
    // bf16 a tile, 16 pixels x 128 channels, pitch 136 (=272B, conflict-free ldmatrix)
    __shared__ __align__(16) unsigned short a_s[2][16][136];   // 8704 B
    __shared__ float norm_s[4][2];

    const int tid = threadIdx.x;
    const int w = tid >> 5;          // warp id
    const int t = tid & 31;          // lane
    const int g = t >> 2;            // row group (pixel row in tile)
    const int q = t & 3;
    const int p0 = blockIdx.x * 16;  // first pixel of this tile

    // ---- Wr B-fragments (bf16, pinned in regs): B[k=c][n=o] = Wr[o][c] ----
    unsigned wb[4][8][2];
#pragma unroll
    for (int nt = 0; nt < 4; nt++) {
        const int n = 32 * w + nt * 8 + (t >> 2);
#pragma unroll
        for (int kk = 0; kk < 8; kk++) {
            const int k0 = kk * 16 + q * 2;
            float2 lo = *reinterpret_cast<const float2*>(wrec + n * C_OUT + k0);
            float2 hi = *reinterpret_cast<const float2*>(wrec + n * C_OUT + k0 + 8);
            wb[nt][kk][0] = pack_bf16(lo.y, lo.x);
            wb[nt][kk][1] = pack_bf16(hi.y, hi.x);
        }
    }

    // ---- u0 fragments + thresholds ----
    float u0f[4][4], thrf[4][2], u[4][4];
#pragma unroll
    for (int nt = 0; nt < 4; nt++) {
        const int cb = 32 * w + nt * 8 + q * 2;
        float2 r0 = *reinterpret_cast<const float2*>(g_u0 + (size_t)(p0 + g) * C_OUT + cb);
        float2 r1 = *reinterpret_cast<const float2*>(g_u0 + (size_t)(p0 + g + 8) * C_OUT + cb);
        u0f[nt][0] = r0.x; u0f[nt][1] = r0.y; u0f[nt][2] = r1.x; u0f[nt][3] = r1.y;
        thrf[nt][0] = thrg[cb]; thrf[nt][1] = thrg[cb + 1];
        u[nt][0] = u[nt][1] = u[nt][2] = u[nt][3] = 0.0f;
    }

    // ---- a0 = relu(u0) into buffer 0 ----
#pragma unroll
    for (int nt = 0; nt < 4; nt++) {
        const int cb = 32 * w + nt * 8 + q * 2;
        *reinterpret_cast<unsigned*>(&a_s[0][g][cb]) =
            pack_bf16(fmaxf(u0f[nt][1], 0.0f), fmaxf(u0f[nt][0], 0.0f));
        *reinterpret_cast<unsigned*>(&a_s[0][g + 8][cb]) =
            pack_bf16(fmaxf(u0f[nt][3], 0.0f), fmaxf(u0f[nt][2], 0.0f));
    }
    __syncthreads();

    // ldmatrix lane addressing (constant per lane)
    const int lrow = (t & 7) + 8 * ((t >> 3) & 1);
    const int lkof = 16 * (t >> 4);   // bytes offset = element*2 -> handled below

    int buf = 0;
    for (int it = 0; it < 200; it++) {
        // lateral = a_s[buf] (16x128) @ WrB (128x32-slice)
        float d[4][4];
#pragma unroll
        for (int nt = 0; nt < 4; nt++)
#pragma unroll
            for (int e = 0; e < 4; e++) d[nt][e] = 0.0f;

#pragma unroll
        for (int kk = 0; kk < 8; kk++) {
            unsigned a0, a1, a2, a3;
            unsigned addr = sm_u32(&a_s[buf][lrow][0]) + kk * 32 + lkof;
            ldmatrix_x4(a0, a1, a2, a3, addr);
#pragma unroll
            for (int nt = 0; nt < 4; nt++)
                mma_bf16(d[nt][0], d[nt][1], d[nt][2], d[nt][3],
                         a0, a1, a2, a3, wb[nt][kk][0], wb[nt][kk][1]);
        }

        // u update + local norm stats + a_new into other buffer
        const int nb = buf ^ 1;
        float sdu = 0.0f, sun = 0.0f;
#pragma unroll
        for (int nt = 0; nt < 4; nt++) {
            const int cb = 32 * w + nt * 8 + q * 2;
            float un[4], av[4];
#pragma unroll
            for (int e = 0; e < 4; e++) {
                float v = fmaf(0.8f, u[nt][e], 0.2f * (u0f[nt][e] - d[nt][e]));
                float du = v - u[nt][e];
                sdu = fmaf(du, du, sdu);
                sun = fmaf(v, v, sun);
                un[e] = v;
                av[e] = fmaxf(v - thrf[nt][e & 1], 0.0f);
                u[nt][e] = v;
            }
            *reinterpret_cast<unsigned*>(&a_s[nb][g][cb])     = pack_bf16(av[1], av[0]);
            *reinterpret_cast<unsigned*>(&a_s[nb][g + 8][cb]) = pack_bf16(av[3], av[2]);
        }

        // warp reduce stats
#pragma unroll
        for (int m = 16; m; m >>= 1) {
            sdu += __shfl_xor_sync(0xffffffffu, sdu, m);
            sun += __shfl_xor_sync(0xffffffffu, sun, m);
        }
        if (t == 0) { norm_s[w][0] = sdu; norm_s[w][1] = sun; }
        __syncthreads();

        float SD = norm_s[0][0] + norm_s[1][0] + norm_s[2][0] + norm_s[3][0];
        float SU = norm_s[0][1] + norm_s[1][1] + norm_s[2][1] + norm_s[3][1];
        // reference: continue while (i==0 || ||du||/||u|| >= 1e-4)
        if (it > 0 && SD <= 1.0e-8f * SU) break;
        buf = nb;
    }

    // ---- final store: a = relu(u - thr), restage to [oc][pix] then NCHW ----
    float* stage = reinterpret_cast<float*>(a_s);   // 128*17 floats = 8704 B, exact alias
#pragma unroll
    for (int nt = 0; nt < 4; nt++) {
        const int cb = 32 * w + nt * 8 + q * 2;
#pragma unroll
        for (int e = 0; e < 4; e++) {
            float av = fmaxf(u[nt][e] - thrf[nt][e & 1], 0.0f);
            int oc = cb + (e & 1);
            int row = g + 8 * (e >> 1);
            stage[oc * 17 + row] = av;
        }
    }
    __syncwarp();

    const int oc = 32 * w + t;
    const int bb = p0 / PIX_PER_IMG;
    const int rem0 = p0 - bb * PIX_PER_IMG;
#pragma unroll
    for (int e = 0; e < 16; e++) {
        int rem = rem0 + e;
        int bcur = bb;
        if (rem >= PIX_PER_IMG) { rem -= PIX_PER_IMG; bcur++; }
        out[((size_t)bcur * C_OUT + oc) * PIX_PER_IMG + rem] = stage[oc * 17 + e];
    }
}

// ---------------------------------------------------------------------------
extern "C" void kernel_launch(void* const* d_in, const int* in_sizes, int n_in,
                              void* d_out, int out_size) {
    const float* x    = (const float*)d_in[0];   // (64,64,64,64)
    const float* wff  = (const float*)d_in[1];   // (128,64,3,3)
    const float* wrec = (const float*)d_in[2];   // (128,128,1,1)
    const float* thr  = (const float*)d_in[3];   // (128,)
    float* out = (float*)d_out;                  // (64,128,62,62)

    conv_kernel<<<dim3(H_OUT, B_SZ), 256>>>(x, wff);
    iter_kernel<<<NPIX / 16, 128>>>(wrec, thr, out);
}

// round 2
// speedup vs baseline: 1.5753x; 1.5753x over previous
#include <cuda_runtime.h>
#include <cuda_bf16.h>
#include <cstdint>

#define C_OUT  128
#define H_OUT  62
#define W_OUT  62
#define PIX_PER_IMG (H_OUT * W_OUT)            // 3844
#define NPIX  (64 * PIX_PER_IMG)               // 246016

// Scratch (static device arrays; no allocation)
__device__ float         g_u0[(size_t)NPIX * C_OUT];        // u0 pixel-major [p][128]
__device__ __nv_bfloat16 g_xh[(size_t)64 * 64 * 64 * 64];   // x transposed [b][h][w][ic], hi
__device__ __nv_bfloat16 g_xl[(size_t)64 * 64 * 64 * 64];   // lo
__device__ __nv_bfloat16 g_wh[9 * 128 * 72];                // W packed [s][o][ic(pad72)], hi
__device__ __nv_bfloat16 g_wl[9 * 128 * 72];                // lo

// ---------------------------------------------------------------------------
// helpers
// ---------------------------------------------------------------------------
__device__ __forceinline__ unsigned pack_bf16(float hi, float lo) {
    unsigned r;
    asm("cvt.rn.bf16x2.f32 %0, %1, %2;" : "=r"(r) : "f"(hi), "f"(lo));
    return r;
}
__device__ __forceinline__ unsigned sm_u32(const void* p) {
    return (unsigned)__cvta_generic_to_shared(p);
}
__device__ __forceinline__ void ldmatrix_x4(unsigned& r0, unsigned& r1,
                                            unsigned& r2, unsigned& r3,
                                            unsigned addr) {
    asm volatile("ldmatrix.sync.aligned.m8n8.x4.shared.b16 {%0,%1,%2,%3}, [%4];"
                 : "=r"(r0), "=r"(r1), "=r"(r2), "=r"(r3) : "r"(addr));
}
__device__ __forceinline__ void mma_bf16(float& d0, float& d1, float& d2, float& d3,
                                         unsigned a0, unsigned a1, unsigned a2, unsigned a3,
                                         unsigned b0, unsigned b1) {
    asm volatile(
        "mma.sync.aligned.m16n8k16.row.col.f32.bf16.bf16.f32 "
        "{%0,%1,%2,%3}, {%4,%5,%6,%7}, {%8,%9}, {%0,%1,%2,%3};"
        : "+f"(d0), "+f"(d1), "+f"(d2), "+f"(d3)
        : "r"(a0), "r"(a1), "r"(a2), "r"(a3), "r"(b0), "r"(b1));
}

// ---------------------------------------------------------------------------
// prep_x: x[b][ic][h][w] fp32  ->  g_xh/g_xl [b][h][w][ic] bf16 (hi/lo split)
// ---------------------------------------------------------------------------
__global__ __launch_bounds__(256)
void prep_x(const float* __restrict__ x) {
    __shared__ float ts[64][65];
    const int b = blockIdx.y, h = blockIdx.x, tid = threadIdx.x;
    const float* src = x + (size_t)b * 262144 + h * 64;
    for (int i = tid; i < 4096; i += 256) {
        int ic = i >> 6, w_ = i & 63;
        ts[w_][ic] = src[(size_t)ic * 4096 + w_];
    }
    __syncthreads();
    const size_t ob = (size_t)b * 262144 + (size_t)h * 4096;
    for (int i = tid; i < 4096; i += 256) {
        int w_ = i >> 6, ic = i & 63;
        float v = ts[w_][ic];
        __nv_bfloat16 hi = __float2bfloat16(v);
        g_xh[ob + i] = hi;
        g_xl[ob + i] = __float2bfloat16(v - __bfloat162float(hi));
    }
}

// ---------------------------------------------------------------------------
// prep_w: wff[o][ic][ky][kx] fp32 -> g_wh/g_wl [s=ky*3+kx][o][ic pad 72] bf16
// ---------------------------------------------------------------------------
__global__ void prep_w(const float* __restrict__ wff) {
    int idx = blockIdx.x * 256 + threadIdx.x;
    if (idx >= 9 * 128 * 72) return;
    int s = idx / 9216, r = idx % 9216, o = r / 72, ic = r % 72;
    float v = (ic < 64) ? wff[o * 576 + ic * 9 + s] : 0.0f;
    __nv_bfloat16 hi = __float2bfloat16(v);
    g_wh[idx] = hi;
    g_wl[idx] = __float2bfloat16(v - __bfloat162float(hi));
}

// ---------------------------------------------------------------------------
// conv2: bf16x3 tensor-core conv. One block = one (b, y): 64 pixels x 128 oc.
// GEMM per (ky,kx): A[m=pixel][k=ic] @ B[n=oc][k=ic]^T, 3-pass hi/lo.
// ---------------------------------------------------------------------------
__global__ __launch_bounds__(128, 2)
void conv2() {
    extern __shared__ __nv_bfloat16 sm[];
    __nv_bfloat16* xh = sm;            // [3][66][72] = 14256
    __nv_bfloat16* xl = xh + 14256;
    __nv_bfloat16* wh = xl + 14256;    // [128][72]  = 9216
    __nv_bfloat16* wl = wh + 9216;

    const int tid = threadIdx.x, w = tid >> 5, t = tid & 31;
    const int y = blockIdx.x, b = blockIdx.y;

    // ---- load x slab: rows y..y+2, cols 0..63, ic 0..63 ----
    {
        const __nv_bfloat16* gh = g_xh + ((size_t)(b * 64 + y) << 12);
        const __nv_bfloat16* gl = g_xl + ((size_t)(b * 64 + y) << 12);
        for (int i = tid; i < 1536; i += 128) {
            int r = i >> 9, rem = i & 511;
            int w_ = rem >> 3, ic8 = (rem & 7) << 3;
            int go = (r << 12) + (w_ << 6) + ic8;
            int so = (r * 66 + w_) * 72 + ic8;
            *(uint4*)(xh + so) = *(const uint4*)(gh + go);
            *(uint4*)(xl + so) = *(const uint4*)(gl + go);
        }
        // zero pad cols 64,65 (read by padded pixels m=62..63)
        for (int i = tid; i < 432; i += 128) {
            int r = i / 144, c = (i % 144) / 72, k = i % 72;
            ((unsigned short*)xh)[(r * 66 + 64 + c) * 72 + k] = 0;
            ((unsigned short*)xl)[(r * 66 + 64 + c) * 72 + k] = 0;
        }
    }

    float d[4][4][4];
#pragma unroll
    for (int mt = 0; mt < 4; mt++)
#pragma unroll
        for (int nt = 0; nt < 4; nt++)
#pragma unroll
            for (int e = 0; e < 4; e++) d[mt][nt][e] = 0.0f;

    const int lm8 = t & 7, lt = t >> 3;
    const int a_row = (lt & 1) * 8 + lm8, a_k = (lt >> 1) * 8;   // A tile order a0,a1,a2,a3
    const int b_row = (lt >> 1) * 8 + lm8, b_k = (lt & 1) * 8;   // B tile order b0,b1 per n-oct
    const unsigned xh0 = sm_u32(xh), xl0 = sm_u32(xl);
    const unsigned wh0 = sm_u32(wh), wl0 = sm_u32(wl);

#pragma unroll 1
    for (int s = 0; s < 9; s++) {
        __syncthreads();   // prior step's ldmatrix reads of W done
        for (int i = tid; i < 1152; i += 128) {
            int o = i / 9, ic8 = (i % 9) << 3;
            int so = o * 72 + ic8, go = (s * 128 + o) * 72 + ic8;
            *(uint4*)(wh + so) = *(const uint4*)(g_wh + go);
            *(uint4*)(wl + so) = *(const uint4*)(g_wl + go);
        }
        __syncthreads();

        const int ky = s / 3, kx = s - ky * 3;
        const unsigned ab_h = xh0 + (unsigned)((ky * 66 + kx) * 72 * 2);
        const unsigned ab_l = xl0 + (unsigned)((ky * 66 + kx) * 72 * 2);

#pragma unroll
        for (int kt = 0; kt < 4; kt++) {
            unsigned bh[4][2], bl[4][2];
            const unsigned wbo = (unsigned)(((w * 32 + b_row) * 72 + kt * 16 + b_k) * 2);
            ldmatrix_x4(bh[0][0], bh[0][1], bh[1][0], bh[1][1], wh0 + wbo);
            ldmatrix_x4(bh[2][0], bh[2][1], bh[3][0], bh[3][1], wh0 + wbo + 16 * 144);
            ldmatrix_x4(bl[0][0], bl[0][1], bl[1][0], bl[1][1], wl0 + wbo);
            ldmatrix_x4(bl[2][0], bl[2][1], bl[3][0], bl[3][1], wl0 + wbo + 16 * 144);
#pragma unroll
            for (int mt = 0; mt < 4; mt++) {
                const unsigned ao = (unsigned)(((mt * 16 + a_row) * 72 + kt * 16 + a_k) * 2);
                unsigned ah0, ah1, ah2, ah3, al0, al1, al2, al3;
                ldmatrix_x4(ah0, ah1, ah2, ah3, ab_h + ao);
                ldmatrix_x4(al0, al1, al2, al3, ab_l + ao);
#pragma unroll
                for (int nt = 0; nt < 4; nt++) {
                    mma_bf16(d[mt][nt][0], d[mt][nt][1], d[mt][nt][2], d[mt][nt][3],
                             ah0, ah1, ah2, ah3, bh[nt][0], bh[nt][1]);
                    mma_bf16(d[mt][nt][0], d[mt][nt][1], d[mt][nt][2], d[mt][nt][3],
                             ah0, ah1, ah2, ah3, bl[nt][0], bl[nt][1]);
                    mma_bf16(d[mt][nt][0], d[mt][nt][1], d[mt][nt][2], d[mt][nt][3],
                             al0, al1, al2, al3, bh[nt][0], bh[nt][1]);
                }
            }
        }
    }

    // ---- store u0 pixel-major ----
    const int p0 = b * PIX_PER_IMG + y * W_OUT;
    const int q = t & 3, g = t >> 2;
#pragma unroll
    for (int mt = 0; mt < 4; mt++) {
#pragma unroll
        for (int nt = 0; nt < 4; nt++) {
            const int ch = w * 32 + nt * 8 + q * 2;
            const int m = mt * 16 + g;
            if (m < W_OUT)
                *(float2*)(g_u0 + (size_t)(p0 + m) * C_OUT + ch) =
                    make_float2(d[mt][nt][0], d[mt][nt][1]);
            if (m + 8 < W_OUT)
                *(float2*)(g_u0 + (size_t)(p0 + m + 8) * C_OUT + ch) =
                    make_float2(d[mt][nt][2], d[mt][nt][3]);
        }
    }
}

// ---------------------------------------------------------------------------
// iter_kernel: fixed-point iteration, 32 pixels/block (2 M-tiles per warp),
// 4 warps x 32 channels. u in mma accumulators; a via double-buffered SMEM.
// ---------------------------------------------------------------------------
__global__ __launch_bounds__(128, 2)
void iter_kernel(const float* __restrict__ wrec, const float* __restrict__ thrg,
                 float* __restrict__ out) {
    __shared__ __align__(16) unsigned short a_s[2][32][136];   // 17408 B
    __shared__ float norm_s[4][2];

    const int tid = threadIdx.x;
    const int w = tid >> 5, t = tid & 31;
    const int g = t >> 2, q = t & 3;
    const int p0 = blockIdx.x * 32;

    // ---- Wr B-fragments in regs ----
    unsigned wb[4][8][2];
#pragma unroll
    for (int nt = 0; nt < 4; nt++) {
        const int n = 32 * w + nt * 8 + (t >> 2);
#pragma unroll
        for (int kk = 0; kk < 8; kk++) {
            const int k0 = kk * 16 + q * 2;
            float2 lo = *reinterpret_cast<const float2*>(wrec + n * C_OUT + k0);
            float2 hi = *reinterpret_cast<const float2*>(wrec + n * C_OUT + k0 + 8);
            wb[nt][kk][0] = pack_bf16(lo.y, lo.x);
            wb[nt][kk][1] = pack_bf16(hi.y, hi.x);
        }
    }

    // ---- u0 fragments (2 tiles) + thresholds ----
    float u0f[2][4][4], thrf[4][2], u[2][4][4];
#pragma unroll
    for (int tt = 0; tt < 2; tt++)
#pragma unroll
        for (int nt = 0; nt < 4; nt++) {
            const int cb = 32 * w + nt * 8 + q * 2;
            const int pr = p0 + tt * 16 + g;
            float2 r0 = *reinterpret_cast<const float2*>(g_u0 + (size_t)pr * C_OUT + cb);
            float2 r1 = *reinterpret_cast<const float2*>(g_u0 + (size_t)(pr + 8) * C_OUT + cb);
            u0f[tt][nt][0] = r0.x; u0f[tt][nt][1] = r0.y;
            u0f[tt][nt][2] = r1.x; u0f[tt][nt][3] = r1.y;
            u[tt][nt][0] = u[tt][nt][1] = u[tt][nt][2] = u[tt][nt][3] = 0.0f;
        }
#pragma unroll
    for (int nt = 0; nt < 4; nt++) {
        const int cb = 32 * w + nt * 8 + q * 2;
        thrf[nt][0] = thrg[cb]; thrf[nt][1] = thrg[cb + 1];
    }

    // ---- a0 = relu(u0) into buffer 0 ----
#pragma unroll
    for (int tt = 0; tt < 2; tt++)
#pragma unroll
        for (int nt = 0; nt < 4; nt++) {
            const int cb = 32 * w + nt * 8 + q * 2;
            *reinterpret_cast<unsigned*>(&a_s[0][tt * 16 + g][cb]) =
                pack_bf16(fmaxf(u0f[tt][nt][1], 0.0f), fmaxf(u0f[tt][nt][0], 0.0f));
            *reinterpret_cast<unsigned*>(&a_s[0][tt * 16 + g + 8][cb]) =
                pack_bf16(fmaxf(u0f[tt][nt][3], 0.0f), fmaxf(u0f[tt][nt][2], 0.0f));
        }
    __syncthreads();

    const int lrow = (t & 7) + 8 * ((t >> 3) & 1);
    const int lkof = 16 * (t >> 4);

    int buf = 0;
    for (int it = 0; it < 200; it++) {
        float dd[2][4][4];
#pragma unroll
        for (int tt = 0; tt < 2; tt++)
#pragma unroll
            for (int nt = 0; nt < 4; nt++)
#pragma unroll
                for (int e = 0; e < 4; e++) dd[tt][nt][e] = 0.0f;

#pragma unroll
        for (int kk = 0; kk < 8; kk++) {
            unsigned a0, a1, a2, a3, c0, c1, c2, c3;
            const unsigned addr0 = sm_u32(&a_s[buf][lrow][0]) + kk * 32 + lkof;
            ldmatrix_x4(a0, a1, a2, a3, addr0);
            ldmatrix_x4(c0, c1, c2, c3, addr0 + 16 * 272);
#pragma unroll
            for (int nt = 0; nt < 4; nt++)
                mma_bf16(dd[0][nt][0], dd[0][nt][1], dd[0][nt][2], dd[0][nt][3],
                         a0, a1, a2, a3, wb[nt][kk][0], wb[nt][kk][1]);
#pragma unroll
            for (int nt = 0; nt < 4; nt++)
                mma_bf16(dd[1][nt][0], dd[1][nt][1], dd[1][nt][2], dd[1][nt][3],
                         c0, c1, c2, c3, wb[nt][kk][0], wb[nt][kk][1]);
        }

        const int nb = buf ^ 1;
        const bool check = (it & 1);
        float sdu = 0.0f, sun = 0.0f;
#pragma unroll
        for (int tt = 0; tt < 2; tt++)
#pragma unroll
            for (int nt = 0; nt < 4; nt++) {
                const int cb = 32 * w + nt * 8 + q * 2;
                float av[4];
#pragma unroll
                for (int e = 0; e < 4; e++) {
                    float v = fmaf(0.8f, u[tt][nt][e], 0.2f * (u0f[tt][nt][e] - dd[tt][nt][e]));
                    if (check) {
                        float du = v - u[tt][nt][e];
                        sdu = fmaf(du, du, sdu);
                        sun = fmaf(v, v, sun);
                    }
                    av[e] = fmaxf(v - thrf[nt][e & 1], 0.0f);
                    u[tt][nt][e] = v;
                }
                *reinterpret_cast<unsigned*>(&a_s[nb][tt * 16 + g][cb])     = pack_bf16(av[1], av[0]);
                *reinterpret_cast<unsigned*>(&a_s[nb][tt * 16 + g + 8][cb]) = pack_bf16(av[3], av[2]);
            }

        if (check) {
#pragma unroll
            for (int m = 16; m; m >>= 1) {
                sdu += __shfl_xor_sync(0xffffffffu, sdu, m);
                sun += __shfl_xor_sync(0xffffffffu, sun, m);
            }
            if (t == 0) { norm_s[w][0] = sdu; norm_s[w][1] = sun; }
        }
        __syncthreads();
        if (check) {
            float SD = norm_s[0][0] + norm_s[1][0] + norm_s[2][0] + norm_s[3][0];
            float SU = norm_s[0][1] + norm_s[1][1] + norm_s[2][1] + norm_s[3][1];
            if (SD <= 1.0e-8f * SU) break;
        }
        buf = nb;
    }

    // ---- final store: a = relu(u - thr), restage [oc][32] then NCHW ----
    float* stage = reinterpret_cast<float*>(a_s);   // 128*33*4 = 16896 <= 17408
#pragma unroll
    for (int tt = 0; tt < 2; tt++)
#pragma unroll
        for (int nt = 0; nt < 4; nt++) {
            const int cb = 32 * w + nt * 8 + q * 2;
#pragma unroll
            for (int e = 0; e < 4; e++) {
                float av = fmaxf(u[tt][nt][e] - thrf[nt][e & 1], 0.0f);
                int oc = cb + (e & 1);
                int row = tt * 16 + g + 8 * (e >> 1);
                stage[oc * 33 + row] = av;
            }
        }
    __syncwarp();

    const int oc = 32 * w + t;
    int bb = p0 / PIX_PER_IMG;
    int rem = p0 - bb * PIX_PER_IMG;
#pragma unroll
    for (int e = 0; e < 32; e++) {
        out[((size_t)bb * C_OUT + oc) * PIX_PER_IMG + rem] = stage[oc * 33 + e];
        if (++rem == PIX_PER_IMG) { rem = 0; bb++; }
    }
}

// ---------------------------------------------------------------------------
extern "C" void kernel_launch(void* const* d_in, const int* in_sizes, int n_in,
                              void* d_out, int out_size) {
    const float* x    = (const float*)d_in[0];   // (64,64,64,64)
    const float* wff  = (const float*)d_in[1];   // (128,64,3,3)
    const float* wrec = (const float*)d_in[2];   // (128,128,1,1)
    const float* thr  = (const float*)d_in[3];   // (128,)
    float* out = (float*)d_out;                  // (64,128,62,62)

    cudaFuncSetAttribute(conv2, cudaFuncAttributeMaxDynamicSharedMemorySize, 93888);

    prep_x<<<dim3(64, 64), 256>>>(x);
    prep_w<<<(9 * 128 * 72 + 255) / 256, 256>>>(wff);
    conv2<<<dim3(H_OUT, 64), 128, 93888>>>();
    iter_kernel<<<NPIX / 32, 128>>>(wrec, thr, out);
}

// round 5
// speedup vs baseline: 1.7832x; 1.1320x over previous
#include <cuda_runtime.h>
#include <cuda_bf16.h>
#include <cstdint>

#define C_OUT  128
#define H_OUT  62
#define W_OUT  62
#define PIX_PER_IMG (H_OUT * W_OUT)            // 3844
#define NPIX  (64 * PIX_PER_IMG)               // 246016

// Scratch (static device arrays; no allocation)
__device__ float         g_u0[(size_t)NPIX * C_OUT];        // u0 pixel-major [p][128]
__device__ __nv_bfloat16 g_xh[(size_t)64 * 64 * 64 * 64];   // x transposed [b][h][w][ic], hi
__device__ __nv_bfloat16 g_xl[(size_t)64 * 64 * 64 * 64];   // lo
__device__ __nv_bfloat16 g_wh[9 * 128 * 72];                // W packed [s][o][ic(pad72)], hi
__device__ __nv_bfloat16 g_wl[9 * 128 * 72];                // lo

// ---------------------------------------------------------------------------
// helpers
// ---------------------------------------------------------------------------
__device__ __forceinline__ unsigned pack_bf16(float hi, float lo) {
    unsigned r;
    asm("cvt.rn.bf16x2.f32 %0, %1, %2;" : "=r"(r) : "f"(hi), "f"(lo));
    return r;
}
__device__ __forceinline__ unsigned sm_u32(const void* p) {
    return (unsigned)__cvta_generic_to_shared(p);
}
__device__ __forceinline__ void ldmatrix_x4(unsigned& r0, unsigned& r1,
                                            unsigned& r2, unsigned& r3,
                                            unsigned addr) {
    asm volatile("ldmatrix.sync.aligned.m8n8.x4.shared.b16 {%0,%1,%2,%3}, [%4];"
                 : "=r"(r0), "=r"(r1), "=r"(r2), "=r"(r3) : "r"(addr));
}
__device__ __forceinline__ void mma_bf16(float& d0, float& d1, float& d2, float& d3,
                                         unsigned a0, unsigned a1, unsigned a2, unsigned a3,
                                         unsigned b0, unsigned b1) {
    asm volatile(
        "mma.sync.aligned.m16n8k16.row.col.f32.bf16.bf16.f32 "
        "{%0,%1,%2,%3}, {%4,%5,%6,%7}, {%8,%9}, {%0,%1,%2,%3};"
        : "+f"(d0), "+f"(d1), "+f"(d2), "+f"(d3)
        : "r"(a0), "r"(a1), "r"(a2), "r"(a3), "r"(b0), "r"(b1));
}

// ---------------------------------------------------------------------------
// prep_x: x[b][ic][h][w] fp32  ->  g_xh/g_xl [b][h][w][ic] bf16 (hi/lo split)
// ---------------------------------------------------------------------------
__global__ __launch_bounds__(256)
void prep_x(const float* __restrict__ x) {
    __shared__ float ts[64][65];
    const int b = blockIdx.y, h = blockIdx.x, tid = threadIdx.x;
    const float* src = x + (size_t)b * 262144 + h * 64;
    for (int i = tid; i < 4096; i += 256) {
        int ic = i >> 6, w_ = i & 63;
        ts[w_][ic] = src[(size_t)ic * 4096 + w_];
    }
    __syncthreads();
    const size_t ob = (size_t)b * 262144 + (size_t)h * 4096;
    for (int i = tid; i < 4096; i += 256) {
        int w_ = i >> 6, ic = i & 63;
        float v = ts[w_][ic];
        __nv_bfloat16 hi = __float2bfloat16(v);
        g_xh[ob + i] = hi;
        g_xl[ob + i] = __float2bfloat16(v - __bfloat162float(hi));
    }
}

// ---------------------------------------------------------------------------
// prep_w: wff[o][ic][ky][kx] fp32 -> g_wh/g_wl [s=ky*3+kx][o][ic pad 72] bf16
// ---------------------------------------------------------------------------
__global__ void prep_w(const float* __restrict__ wff) {
    int idx = blockIdx.x * 256 + threadIdx.x;
    if (idx >= 9 * 128 * 72) return;
    int s = idx / 9216, r = idx % 9216, o = r / 72, ic = r % 72;
    float v = (ic < 64) ? wff[o * 576 + ic * 9 + s] : 0.0f;
    __nv_bfloat16 hi = __float2bfloat16(v);
    g_wh[idx] = hi;
    g_wl[idx] = __float2bfloat16(v - __bfloat162float(hi));
}

// ---------------------------------------------------------------------------
// conv2: bf16x3 tensor-core conv. One block = one (b, y): 64 pixels x 128 oc.
// ---------------------------------------------------------------------------
__global__ __launch_bounds__(128, 2)
void conv2() {
    extern __shared__ __nv_bfloat16 sm[];
    __nv_bfloat16* xh = sm;            // [3][66][72] = 14256
    __nv_bfloat16* xl = xh + 14256;
    __nv_bfloat16* wh = xl + 14256;    // [128][72]  = 9216
    __nv_bfloat16* wl = wh + 9216;

    const int tid = threadIdx.x, w = tid >> 5, t = tid & 31;
    const int y = blockIdx.x, b = blockIdx.y;

    {
        const __nv_bfloat16* gh = g_xh + ((size_t)(b * 64 + y) << 12);
        const __nv_bfloat16* gl = g_xl + ((size_t)(b * 64 + y) << 12);
        for (int i = tid; i < 1536; i += 128) {
            int r = i >> 9, rem = i & 511;
            int w_ = rem >> 3, ic8 = (rem & 7) << 3;
            int go = (r << 12) + (w_ << 6) + ic8;
            int so = (r * 66 + w_) * 72 + ic8;
            *(uint4*)(xh + so) = *(const uint4*)(gh + go);
            *(uint4*)(xl + so) = *(const uint4*)(gl + go);
        }
        for (int i = tid; i < 432; i += 128) {
            int r = i / 144, c = (i % 144) / 72, k = i % 72;
            ((unsigned short*)xh)[(r * 66 + 64 + c) * 72 + k] = 0;
            ((unsigned short*)xl)[(r * 66 + 64 + c) * 72 + k] = 0;
        }
    }

    float d[4][4][4];
#pragma unroll
    for (int mt = 0; mt < 4; mt++)
#pragma unroll
        for (int nt = 0; nt < 4; nt++)
#pragma unroll
            for (int e = 0; e < 4; e++) d[mt][nt][e] = 0.0f;

    const int lm8 = t & 7, lt = t >> 3;
    const int a_row = (lt & 1) * 8 + lm8, a_k = (lt >> 1) * 8;
    const int b_row = (lt >> 1) * 8 + lm8, b_k = (lt & 1) * 8;
    const unsigned xh0 = sm_u32(xh), xl0 = sm_u32(xl);
    const unsigned wh0 = sm_u32(wh), wl0 = sm_u32(wl);

#pragma unroll 1
    for (int s = 0; s < 9; s++) {
        __syncthreads();
        for (int i = tid; i < 1152; i += 128) {
            int o = i / 9, ic8 = (i % 9) << 3;
            int so = o * 72 + ic8, go = (s * 128 + o) * 72 + ic8;
            *(uint4*)(wh + so) = *(const uint4*)(g_wh + go);
            *(uint4*)(wl + so) = *(const uint4*)(g_wl + go);
        }
        __syncthreads();

        const int ky = s / 3, kx = s - ky * 3;
        const unsigned ab_h = xh0 + (unsigned)((ky * 66 + kx) * 72 * 2);
        const unsigned ab_l = xl0 + (unsigned)((ky * 66 + kx) * 72 * 2);

#pragma unroll
        for (int kt = 0; kt < 4; kt++) {
            unsigned bh[4][2], bl[4][2];
            const unsigned wbo = (unsigned)(((w * 32 + b_row) * 72 + kt * 16 + b_k) * 2);
            ldmatrix_x4(bh[0][0], bh[0][1], bh[1][0], bh[1][1], wh0 + wbo);
            ldmatrix_x4(bh[2][0], bh[2][1], bh[3][0], bh[3][1], wh0 + wbo + 16 * 144);
            ldmatrix_x4(bl[0][0], bl[0][1], bl[1][0], bl[1][1], wl0 + wbo);
            ldmatrix_x4(bl[2][0], bl[2][1], bl[3][0], bl[3][1], wl0 + wbo + 16 * 144);
#pragma unroll
            for (int mt = 0; mt < 4; mt++) {
                const unsigned ao = (unsigned)(((mt * 16 + a_row) * 72 + kt * 16 + a_k) * 2);
                unsigned ah0, ah1, ah2, ah3, al0, al1, al2, al3;
                ldmatrix_x4(ah0, ah1, ah2, ah3, ab_h + ao);
                ldmatrix_x4(al0, al1, al2, al3, ab_l + ao);
#pragma unroll
                for (int nt = 0; nt < 4; nt++) {
                    mma_bf16(d[mt][nt][0], d[mt][nt][1], d[mt][nt][2], d[mt][nt][3],
                             ah0, ah1, ah2, ah3, bh[nt][0], bh[nt][1]);
                    mma_bf16(d[mt][nt][0], d[mt][nt][1], d[mt][nt][2], d[mt][nt][3],
                             ah0, ah1, ah2, ah3, bl[nt][0], bl[nt][1]);
                    mma_bf16(d[mt][nt][0], d[mt][nt][1], d[mt][nt][2], d[mt][nt][3],
                             al0, al1, al2, al3, bh[nt][0], bh[nt][1]);
                }
            }
        }
    }

    const int p0 = b * PIX_PER_IMG + y * W_OUT;
    const int q = t & 3, g = t >> 2;
#pragma unroll
    for (int mt = 0; mt < 4; mt++) {
#pragma unroll
        for (int nt = 0; nt < 4; nt++) {
            const int ch = w * 32 + nt * 8 + q * 2;
            const int m = mt * 16 + g;
            if (m < W_OUT)
                *(float2*)(g_u0 + (size_t)(p0 + m) * C_OUT + ch) =
                    make_float2(d[mt][nt][0], d[mt][nt][1]);
            if (m + 8 < W_OUT)
                *(float2*)(g_u0 + (size_t)(p0 + m + 8) * C_OUT + ch) =
                    make_float2(d[mt][nt][2], d[mt][nt][3]);
        }
    }
}

// ---------------------------------------------------------------------------
// iter_kernel v3: D-merged accumulator (D = -5u), 32 pixels/block, 3 blocks/SM.
// Seed D = 0.8D - u0 each iter; MMA adds lateral; a = relu(-0.2D - thr).
// ---------------------------------------------------------------------------
__global__ __launch_bounds__(128, 3)
void iter_kernel(const float* __restrict__ wrec, const float* __restrict__ thrg,
                 float* __restrict__ out) {
    __shared__ __align__(16) unsigned short a_s[2][32][136];   // 17408 B
    __shared__ float norm_s[4][2];

    const int tid = threadIdx.x;
    const int w = tid >> 5, t = tid & 31;
    const int g = t >> 2, q = t & 3;
    const int p0 = blockIdx.x * 32;

    // ---- Wr B-fragments in regs (64) ----
    unsigned wb[4][8][2];
#pragma unroll
    for (int nt = 0; nt < 4; nt++) {
        const int n = 32 * w + nt * 8 + (t >> 2);
#pragma unroll
        for (int kk = 0; kk < 8; kk++) {
            const int k0 = kk * 16 + q * 2;
            float2 lo = *reinterpret_cast<const float2*>(wrec + n * C_OUT + k0);
            float2 hi = *reinterpret_cast<const float2*>(wrec + n * C_OUT + k0 + 8);
            wb[nt][kk][0] = pack_bf16(lo.y, lo.x);
            wb[nt][kk][1] = pack_bf16(hi.y, hi.x);
        }
    }

    // ---- u0 fragments, D init (= -u0), neg thresholds ----
    float u0f[2][4][4], nthr[4][2], D[2][4][4];
#pragma unroll
    for (int tt = 0; tt < 2; tt++)
#pragma unroll
        for (int nt = 0; nt < 4; nt++) {
            const int cb = 32 * w + nt * 8 + q * 2;
            const int pr = p0 + tt * 16 + g;
            float2 r0 = *reinterpret_cast<const float2*>(g_u0 + (size_t)pr * C_OUT + cb);
            float2 r1 = *reinterpret_cast<const float2*>(g_u0 + (size_t)(pr + 8) * C_OUT + cb);
            u0f[tt][nt][0] = r0.x; u0f[tt][nt][1] = r0.y;
            u0f[tt][nt][2] = r1.x; u0f[tt][nt][3] = r1.y;
#pragma unroll
            for (int e = 0; e < 4; e++) D[tt][nt][e] = -u0f[tt][nt][e];
        }
#pragma unroll
    for (int nt = 0; nt < 4; nt++) {
        const int cb = 32 * w + nt * 8 + q * 2;
        nthr[nt][0] = -thrg[cb]; nthr[nt][1] = -thrg[cb + 1];
    }

    // ---- a0 = relu(u0) into buffer 0 ----
#pragma unroll
    for (int tt = 0; tt < 2; tt++)
#pragma unroll
        for (int nt = 0; nt < 4; nt++) {
            const int cb = 32 * w + nt * 8 + q * 2;
            *reinterpret_cast<unsigned*>(&a_s[0][tt * 16 + g][cb]) =
                pack_bf16(fmaxf(u0f[tt][nt][1], 0.0f), fmaxf(u0f[tt][nt][0], 0.0f));
            *reinterpret_cast<unsigned*>(&a_s[0][tt * 16 + g + 8][cb]) =
                pack_bf16(fmaxf(u0f[tt][nt][3], 0.0f), fmaxf(u0f[tt][nt][2], 0.0f));
        }
    __syncthreads();

    const int lrow = (t & 7) + 8 * ((t >> 3) & 1);
    const int lkof = 16 * (t >> 4);

    float stash[8];   // D_pre sample: tt=0, nt=0..1
    int buf = 0;
    for (int it = 0; it < 200; it++) {
        // lateral accumulates into D (seeded with 0.8*D_prev - u0)
#pragma unroll
        for (int kk = 0; kk < 8; kk++) {
            unsigned a0, a1, a2, a3, c0, c1, c2, c3;
            const unsigned addr0 = sm_u32(&a_s[buf][lrow][0]) + kk * 32 + lkof;
            ldmatrix_x4(a0, a1, a2, a3, addr0);
            ldmatrix_x4(c0, c1, c2, c3, addr0 + 16 * 272);
#pragma unroll
            for (int nt = 0; nt < 4; nt++)
                mma_bf16(D[0][nt][0], D[0][nt][1], D[0][nt][2], D[0][nt][3],
                         a0, a1, a2, a3, wb[nt][kk][0], wb[nt][kk][1]);
#pragma unroll
            for (int nt = 0; nt < 4; nt++)
                mma_bf16(D[1][nt][0], D[1][nt][1], D[1][nt][2], D[1][nt][3],
                         c0, c1, c2, c3, wb[nt][kk][0], wb[nt][kk][1]);
        }

        // a_new = relu(-0.2*D - thr) into other buffer
        const int nb = buf ^ 1;
#pragma unroll
        for (int tt = 0; tt < 2; tt++)
#pragma unroll
            for (int nt = 0; nt < 4; nt++) {
                const int cb = 32 * w + nt * 8 + q * 2;
                float av[4];
#pragma unroll
                for (int e = 0; e < 4; e++)
                    av[e] = fmaxf(fmaf(-0.2f, D[tt][nt][e], nthr[nt][e & 1]), 0.0f);
                *reinterpret_cast<unsigned*>(&a_s[nb][tt * 16 + g][cb])     = pack_bf16(av[1], av[0]);
                *reinterpret_cast<unsigned*>(&a_s[nb][tt * 16 + g + 8][cb]) = pack_bf16(av[3], av[2]);
            }

        const bool check = (it & 1);
        if (check) {
            float sdu = 0.0f, sun = 0.0f;
#pragma unroll
            for (int nt = 0; nt < 2; nt++)
#pragma unroll
                for (int e = 0; e < 4; e++) {
                    float df = D[0][nt][e] - stash[nt * 4 + e];
                    sdu = fmaf(df, df, sdu);
                    sun = fmaf(D[0][nt][e], D[0][nt][e], sun);
                }
#pragma unroll
            for (int m = 16; m; m >>= 1) {
                sdu += __shfl_xor_sync(0xffffffffu, sdu, m);
                sun += __shfl_xor_sync(0xffffffffu, sun, m);
            }
            if (t == 0) { norm_s[w][0] = sdu; norm_s[w][1] = sun; }
        }
        __syncthreads();
        if (check) {
            float SD = norm_s[0][0] + norm_s[1][0] + norm_s[2][0] + norm_s[3][0];
            float SU = norm_s[0][1] + norm_s[1][1] + norm_s[2][1] + norm_s[3][1];
            if (SD <= 1.0e-8f * SU) break;
        } else {
            // next iter checks: stash D_after (u_old = -0.2 * this)
#pragma unroll
            for (int nt = 0; nt < 2; nt++)
#pragma unroll
                for (int e = 0; e < 4; e++) stash[nt * 4 + e] = D[0][nt][e];
        }

        // seed for next iteration: D = 0.8*D - u0
#pragma unroll
        for (int tt = 0; tt < 2; tt++)
#pragma unroll
            for (int nt = 0; nt < 4; nt++)
#pragma unroll
                for (int e = 0; e < 4; e++)
                    D[tt][nt][e] = fmaf(0.8f, D[tt][nt][e], -u0f[tt][nt][e]);
        buf = nb;
    }

    // ---- final store: a = relu(-0.2D - thr), restage [oc][32] then NCHW ----
    float* stage = reinterpret_cast<float*>(a_s);   // 128*33*4 = 16896 <= 17408
#pragma unroll
    for (int tt = 0; tt < 2; tt++)
#pragma unroll
        for (int nt = 0; nt < 4; nt++) {
            const int cb = 32 * w + nt * 8 + q * 2;
#pragma unroll
            for (int e = 0; e < 4; e++) {
                float av = fmaxf(fmaf(-0.2f, D[tt][nt][e], nthr[nt][e & 1]), 0.0f);
                int oc = cb + (e & 1);
                int row = tt * 16 + g + 8 * (e >> 1);
                stage[oc * 33 + row] = av;
            }
        }
    __syncwarp();

    const int oc = 32 * w + t;
    int bb = p0 / PIX_PER_IMG;
    int rem = p0 - bb * PIX_PER_IMG;
#pragma unroll
    for (int e = 0; e < 32; e++) {
        out[((size_t)bb * C_OUT + oc) * PIX_PER_IMG + rem] = stage[oc * 33 + e];
        if (++rem == PIX_PER_IMG) { rem = 0; bb++; }
    }
}

// ---------------------------------------------------------------------------
extern "C" void kernel_launch(void* const* d_in, const int* in_sizes, int n_in,
                              void* d_out, int out_size) {
    const float* x    = (const float*)d_in[0];   // (64,64,64,64)
    const float* wff  = (const float*)d_in[1];   // (128,64,3,3)
    const float* wrec = (const float*)d_in[2];   // (128,128,1,1)
    const float* thr  = (const float*)d_in[3];   // (128,)
    float* out = (float*)d_out;                  // (64,128,62,62)

    cudaFuncSetAttribute(conv2, cudaFuncAttributeMaxDynamicSharedMemorySize, 93888);

    prep_x<<<dim3(64, 64), 256>>>(x);
    prep_w<<<(9 * 128 * 72 + 255) / 256, 256>>>(wff);
    conv2<<<dim3(H_OUT, 64), 128, 93888>>>();
    iter_kernel<<<NPIX / 32, 128>>>(wrec, thr, out);
}